// round 14
// baseline (speedup 1.0000x reference)
#include <cuda_runtime.h>
#include <cstdint>

#define T_DIM 256
#define B_DIM 128
#define DIN 20
#define H_DIM 1024
#define OUT_DIM 1095
#define L_DIM 3
#define M_ALL (T_DIM * B_DIM)   // 32768
#define N_SRU (3 * H_DIM)       // 3072
#define N3PAD 1152
#define K8CNT (H_DIM / 8)       // 128
#define KPCNT (K8CNT / 2)       // 64
#define N8_SRU (N_SRU / 8)      // 384
#define N8_W3 (N3PAD / 8)       // 144

// ---------------- scratch ----------------
__device__ float g_U[(size_t)M_ALL * N_SRU];                      // 402 MB
__device__ uint4 g_Af[(size_t)(M_ALL / 16) * K8CNT * 32];         // 134 MB
__device__ float g_WT[(size_t)L_DIM * N_SRU * H_DIM];             // B frags (SRU)
__device__ float g_W3T[(size_t)N3PAD * H_DIM];                    // B frags (W3)

__device__ __forceinline__ uint32_t f2tf32(float v) {
    uint32_t u;
    asm("cvt.rna.tf32.f32 %0, %1;" : "=r"(u) : "f"(v));
    return u;
}

// ---------------------------------------------------------------------------
// Prep B (all layers, one launch): W[K][N] -> fragment-pair order (n8-major)
// ---------------------------------------------------------------------------
__global__ void wfrag_all_kernel(const float* __restrict__ Wsru,
                                 const float* __restrict__ W3,
                                 uint4* __restrict__ BF,
                                 uint4* __restrict__ BF3,
                                 size_t layerStride) {
    const int layer = blockIdx.y;
    const float* W;
    uint4* dst;
    int N, N8;
    if (layer < 3) {
        W = Wsru + (size_t)layer * H_DIM * N_SRU;
        dst = BF + (size_t)layer * layerStride;
        N = N_SRU; N8 = N8_SRU;
    } else {
        W = W3; dst = BF3; N = OUT_DIM; N8 = N8_W3;
    }
    int task = blockIdx.x * 8 + (threadIdx.x >> 5);
    if (task >= N8 * KPCNT) return;
    int n8 = task / KPCNT;
    int kp = task - n8 * KPCNT;
    int lane = threadIdx.x & 31;
    int n = n8 * 8 + (lane >> 2);
    int kq = kp * 16 + (lane & 3);
    float b0 = 0.0f, b1 = 0.0f, b2 = 0.0f, b3 = 0.0f;
    if (n < N) {
        b0 = W[(size_t)kq * N + n];
        b1 = W[(size_t)(kq + 4) * N + n];
        b2 = W[(size_t)(kq + 8) * N + n];
        b3 = W[(size_t)(kq + 12) * N + n];
    }
    dst[((size_t)n8 * KPCNT + kp) * 32 + lane] =
        make_uint4(f2tf32(b0), f2tf32(b1), f2tf32(b2), f2tf32(b3));
}

// ---------------------------------------------------------------------------
// Dense1 -> A fragments directly (verified round 12)
// ---------------------------------------------------------------------------
__global__ void dense1_frag_kernel(const float* __restrict__ x,
                                   const float* __restrict__ W1,
                                   const float* __restrict__ b1v,
                                   uint4* __restrict__ Af) {
    const int m16 = blockIdx.x;
    const int t = m16 >> 3, bg = m16 & 7;
    __shared__ float xs[16][20];
    for (int i = threadIdx.x; i < 16 * DIN; i += blockDim.x) {
        int r = i / DIN, cc = i - r * DIN;
        xs[r][cc] = x[((size_t)t * B_DIM + bg * 16 + r) * DIN + cc];
    }
    __syncthreads();
    const int w = threadIdx.x >> 5, lane = threadIdx.x & 31;
    const int gr = lane >> 2, gc = lane & 3;
    for (int kb = 0; kb < 16; kb++) {
        int k8 = kb * 8 + w;
        int h0 = k8 * 8 + gc, h1 = h0 + 4;
        float a00 = b1v[h0], a01 = b1v[h1];
        float a10 = a00, a11 = a01;
#pragma unroll
        for (int k = 0; k < DIN; k++) {
            float w0 = W1[k * H_DIM + h0], w1 = W1[k * H_DIM + h1];
            float x0 = xs[gr][k], x1 = xs[gr + 8][k];
            a00 += x0 * w0; a01 += x0 * w1;
            a10 += x1 * w0; a11 += x1 * w1;
        }
        Af[((size_t)m16 * K8CNT + k8) * 32 + lane] =
            make_uint4(f2tf32(a00), f2tf32(a10), f2tf32(a01), f2tf32(a11));
    }
}

// ---------------------------------------------------------------------------
// TF32 GEMM, fragment-direct + one-k8-ahead software pipeline.
// B s-halves load as uint2 at byte offsets (kp*512 + s*8) + ni*32768.
// k8 accumulation order 0..127 identical to prior rounds -> bit-identical.
// ---------------------------------------------------------------------------
#define B_NI_STRIDE (KPCNT * 512)         // 32768 bytes
#define A_MI_STRIDE (K8CNT * 512)         // 65536 bytes

template <bool GUARD_N>
__global__ __launch_bounds__(256, 2) void tf32_gemm(
    const uint4* __restrict__ Af, const uint4* __restrict__ Bf,
    float* __restrict__ C, int ldC, int Nvalid, const float* __restrict__ bias) {
    const int tid = threadIdx.x;
    const int lane = tid & 31;
    const int warp = tid >> 5;
    const int wm = warp >> 1;
    const int wn = warp & 1;

    const char* Apb = (const char*)(Af + ((size_t)(blockIdx.y * 8 + wm * 2) * K8CNT) * 32 + lane);
    const char* Bpb = (const char*)(Bf + ((size_t)(blockIdx.x * 16 + wn * 8) * KPCNT) * 32 + lane);

    float acc[2][8][4];
#pragma unroll
    for (int mi = 0; mi < 2; mi++)
#pragma unroll
        for (int ni = 0; ni < 8; ni++)
#pragma unroll
            for (int j = 0; j < 4; j++) acc[mi][ni][j] = 0.0f;

    uint2 bA[8], bB[8];
    uint4 aA[2], aB[2];

#define LOADK8(k8, br, ar) do {                                               \
        uint32_t boff = (uint32_t)(((k8) >> 1) * 512 + ((k8) & 1) * 8);       \
        _Pragma("unroll")                                                     \
        for (int ni = 0; ni < 8; ni++)                                        \
            (br)[ni] = *(const uint2*)(Bpb + ni * B_NI_STRIDE + boff);        \
        uint32_t aoff = (uint32_t)((k8) * 512);                               \
        _Pragma("unroll")                                                     \
        for (int mi = 0; mi < 2; mi++)                                        \
            (ar)[mi] = *(const uint4*)(Apb + mi * A_MI_STRIDE + aoff);        \
    } while (0)

#define MMASTEP(br, ar) do {                                                  \
        _Pragma("unroll")                                                     \
        for (int mi = 0; mi < 2; mi++)                                        \
            _Pragma("unroll")                                                 \
            for (int ni = 0; ni < 8; ni++)                                    \
                asm volatile(                                                 \
                    "mma.sync.aligned.m16n8k8.row.col.f32.tf32.tf32.f32 "     \
                    "{%0,%1,%2,%3}, {%4,%5,%6,%7}, {%8,%9}, {%0,%1,%2,%3};\n" \
                    : "+f"(acc[mi][ni][0]), "+f"(acc[mi][ni][1]),             \
                      "+f"(acc[mi][ni][2]), "+f"(acc[mi][ni][3])              \
                    : "r"((ar)[mi].x), "r"((ar)[mi].y),                       \
                      "r"((ar)[mi].z), "r"((ar)[mi].w),                       \
                      "r"((br)[ni].x), "r"((br)[ni].y));                      \
    } while (0)

    LOADK8(0, bA, aA);
    for (int k8 = 0; k8 < K8CNT; k8 += 2) {
        LOADK8(k8 + 1, bB, aB);
        MMASTEP(bA, aA);
        if (k8 + 2 < K8CNT) LOADK8(k8 + 2, bA, aA);
        MMASTEP(bB, aB);
    }
#undef LOADK8
#undef MMASTEP

    const int gr = lane >> 2;
    const int gc = (lane & 3) * 2;
#pragma unroll
    for (int mi = 0; mi < 2; mi++) {
        int r0 = blockIdx.y * 128 + wm * 32 + mi * 16 + gr;
#pragma unroll
        for (int ni = 0; ni < 8; ni++) {
            int c0 = blockIdx.x * 128 + wn * 64 + ni * 8 + gc;
            float b0 = 0.0f, b1 = 0.0f;
            if (bias) {
                if (!GUARD_N || c0 < Nvalid) b0 = bias[c0];
                if (!GUARD_N || c0 + 1 < Nvalid) b1 = bias[c0 + 1];
            }
            float* Cp0 = C + (size_t)r0 * ldC + c0;
            float* Cp1 = C + (size_t)(r0 + 8) * ldC + c0;
            if (!GUARD_N || c0 < Nvalid) {
                Cp0[0] = acc[mi][ni][0] + b0;
                Cp1[0] = acc[mi][ni][2] + b0;
            }
            if (!GUARD_N || c0 + 1 < Nvalid) {
                Cp0[1] = acc[mi][ni][1] + b1;
                Cp1[1] = acc[mi][ni][3] + b1;
            }
        }
    }
}

// ---------------------------------------------------------------------------
// Fused SRU scan: thread owns chain pair (b, b+8) for one h -> its two Af
// words are one aligned uint2 (comp {2hsel, 2hsel+1} = {bsel0, bsel1}).
// Per warp, each k8's updates are 64B contiguous (full sectors). 65536 thr.
// ---------------------------------------------------------------------------
__global__ void sru_scan_frag_kernel(const float* __restrict__ U,
                                     uint2* __restrict__ Afw,
                                     const float* __restrict__ bfp,
                                     const float* __restrict__ brp,
                                     float* __restrict__ c_out) {
    const int idx = blockIdx.x * blockDim.x + threadIdx.x;   // 0..65535
    const int bp = idx >> 10;          // 0..63
    const int h = idx & 1023;
    const int bg = bp >> 3, gr = bp & 7;
    const int b0 = bg * 16 + gr, b1 = b0 + 8;
    const int k8 = h >> 3, hsel = (h >> 2) & 1, gc = h & 3;
    const int lane = gr * 4 + gc;

    const float bfv = bfp[h];
    const float brv = brp[h];
    float c0 = 0.0f, c1 = 0.0f;

    const float* U0 = U + (size_t)b0 * N_SRU + h;
    const float* U1 = U + (size_t)b1 * N_SRU + h;
    uint2* Ab = Afw + (((size_t)bg * K8CNT + k8) * 128 + lane * 4 + 2 * hsel) / 2;
    const size_t aStep = (size_t)8 * K8CNT * 64;   // uint2 per t

    for (int t = 0; t < T_DIM; t++) {
        const float* u0 = U0 + (size_t)t * B_DIM * N_SRU;
        const float* u1 = U1 + (size_t)t * B_DIM * N_SRU;
        float z0 = u0[0],  fp0 = u0[H_DIM],  rp0 = u0[2 * H_DIM];
        float z1 = u1[0],  fp1 = u1[H_DIM],  rp1 = u1[2 * H_DIM];
        uint2* Ap = Ab + (size_t)t * aStep;
        uint2 hv = *Ap;

        float f0 = 1.0f / (1.0f + __expf(-(fp0 + bfv)));
        float r0 = 1.0f / (1.0f + __expf(-(rp0 + brv)));
        float f1 = 1.0f / (1.0f + __expf(-(fp1 + bfv)));
        float r1 = 1.0f / (1.0f + __expf(-(rp1 + brv)));

        c0 = f0 * c0 + (1.0f - f0) * z0;
        c1 = f1 * c1 + (1.0f - f1) * z1;

        hv.x = f2tf32(r0 * c0 + (1.0f - r0) * __uint_as_float(hv.x));
        hv.y = f2tf32(r1 * c1 + (1.0f - r1) * __uint_as_float(hv.y));
        *Ap = hv;
    }
    c_out[(size_t)b0 * H_DIM + h] = c0;
    c_out[(size_t)b1 * H_DIM + h] = c1;
}

// ---------------------------------------------------------------------------
// Launch
// ---------------------------------------------------------------------------
extern "C" void kernel_launch(void* const* d_in, const int* in_sizes, int n_in,
                              void* d_out, int out_size) {
    const float* x     = (const float*)d_in[0];
    const float* W1    = (const float*)d_in[2];
    const float* b1    = (const float*)d_in[3];
    const float* W_sru = (const float*)d_in[4];
    const float* bf    = (const float*)d_in[5];
    const float* br    = (const float*)d_in[6];
    const float* W3    = (const float*)d_in[7];
    const float* b3    = (const float*)d_in[8];
    float* out = (float*)d_out;

    float *U_buf, *WTf, *W3Tf;
    uint4* Af;
    cudaGetSymbolAddress((void**)&U_buf, g_U);
    cudaGetSymbolAddress((void**)&Af, g_Af);
    cudaGetSymbolAddress((void**)&WTf, g_WT);
    cudaGetSymbolAddress((void**)&W3Tf, g_W3T);
    uint4* BF = (uint4*)WTf;
    uint4* BF3 = (uint4*)W3Tf;
    const size_t bfLayerStride = (size_t)N8_SRU * KPCNT * 32;

    {
        dim3 grd(N8_SRU * KPCNT / 8, 4);
        wfrag_all_kernel<<<grd, 256>>>(W_sru, W3, BF, BF3, bfLayerStride);
    }

    dense1_frag_kernel<<<M_ALL / 16, 256>>>(x, W1, b1, Af);

    float* c_base = out + (size_t)M_ALL * OUT_DIM;
    for (int l = 0; l < L_DIM; l++) {
        dim3 grid(N_SRU / 128, M_ALL / 128);
        tf32_gemm<false><<<grid, 256>>>(
            Af, BF + l * bfLayerStride, U_buf, N_SRU, N_SRU, nullptr);
        sru_scan_frag_kernel<<<(B_DIM * H_DIM / 2) / 256, 256>>>(
            U_buf, (uint2*)Af, bf + l * H_DIM, br + l * H_DIM,
            c_base + (size_t)l * B_DIM * H_DIM);
    }

    dim3 grid3(N3PAD / 128, M_ALL / 128);
    tf32_gemm<true><<<grid3, 256>>>(Af, BF3, out, OUT_DIM, OUT_DIM, b3);
}

// round 15
// speedup vs baseline: 1.1772x; 1.1772x over previous
#include <cuda_runtime.h>
#include <cstdint>

#define T_DIM 256
#define B_DIM 128
#define DIN 20
#define H_DIM 1024
#define OUT_DIM 1095
#define L_DIM 3
#define M_ALL (T_DIM * B_DIM)   // 32768
#define N_SRU (3 * H_DIM)       // 3072
#define N3PAD 1152
#define K8CNT (H_DIM / 8)       // 128
#define KPCNT (K8CNT / 2)       // 64
#define N8_SRU (N_SRU / 8)      // 384
#define N8_W3 (N3PAD / 8)       // 144

// ---------------- scratch ----------------
__device__ float g_U[(size_t)M_ALL * N_SRU];                      // 402 MB
__device__ uint4 g_Af[(size_t)(M_ALL / 16) * K8CNT * 32];         // 134 MB
__device__ float g_WT[(size_t)L_DIM * N_SRU * H_DIM];             // B frags (SRU)
__device__ float g_W3T[(size_t)N3PAD * H_DIM];                    // B frags (W3)

__device__ __forceinline__ uint32_t f2tf32(float v) {
    uint32_t u;
    asm("cvt.rna.tf32.f32 %0, %1;" : "=r"(u) : "f"(v));
    return u;
}

// ---------------------------------------------------------------------------
// Prep B (all layers, one launch): W[K][N] -> fragment-pair order (n8-major)
// ---------------------------------------------------------------------------
__global__ void wfrag_all_kernel(const float* __restrict__ Wsru,
                                 const float* __restrict__ W3,
                                 uint4* __restrict__ BF,
                                 uint4* __restrict__ BF3,
                                 size_t layerStride) {
    const int layer = blockIdx.y;
    const float* W;
    uint4* dst;
    int N, N8;
    if (layer < 3) {
        W = Wsru + (size_t)layer * H_DIM * N_SRU;
        dst = BF + (size_t)layer * layerStride;
        N = N_SRU; N8 = N8_SRU;
    } else {
        W = W3; dst = BF3; N = OUT_DIM; N8 = N8_W3;
    }
    int task = blockIdx.x * 8 + (threadIdx.x >> 5);
    if (task >= N8 * KPCNT) return;
    int n8 = task / KPCNT;
    int kp = task - n8 * KPCNT;
    int lane = threadIdx.x & 31;
    int n = n8 * 8 + (lane >> 2);
    int kq = kp * 16 + (lane & 3);
    float b0 = 0.0f, b1 = 0.0f, b2 = 0.0f, b3 = 0.0f;
    if (n < N) {
        b0 = W[(size_t)kq * N + n];
        b1 = W[(size_t)(kq + 4) * N + n];
        b2 = W[(size_t)(kq + 8) * N + n];
        b3 = W[(size_t)(kq + 12) * N + n];
    }
    dst[((size_t)n8 * KPCNT + kp) * 32 + lane] =
        make_uint4(f2tf32(b0), f2tf32(b1), f2tf32(b2), f2tf32(b3));
}

// ---------------------------------------------------------------------------
// Dense1 -> A fragments directly (verified)
// ---------------------------------------------------------------------------
__global__ void dense1_frag_kernel(const float* __restrict__ x,
                                   const float* __restrict__ W1,
                                   const float* __restrict__ b1v,
                                   uint4* __restrict__ Af) {
    const int m16 = blockIdx.x;
    const int t = m16 >> 3, bg = m16 & 7;
    __shared__ float xs[16][20];
    for (int i = threadIdx.x; i < 16 * DIN; i += blockDim.x) {
        int r = i / DIN, cc = i - r * DIN;
        xs[r][cc] = x[((size_t)t * B_DIM + bg * 16 + r) * DIN + cc];
    }
    __syncthreads();
    const int w = threadIdx.x >> 5, lane = threadIdx.x & 31;
    const int gr = lane >> 2, gc = lane & 3;
    for (int kb = 0; kb < 16; kb++) {
        int k8 = kb * 8 + w;
        int h0 = k8 * 8 + gc, h1 = h0 + 4;
        float a00 = b1v[h0], a01 = b1v[h1];
        float a10 = a00, a11 = a01;
#pragma unroll
        for (int k = 0; k < DIN; k++) {
            float w0 = W1[k * H_DIM + h0], w1 = W1[k * H_DIM + h1];
            float x0 = xs[gr][k], x1 = xs[gr + 8][k];
            a00 += x0 * w0; a01 += x0 * w1;
            a10 += x1 * w0; a11 += x1 * w1;
        }
        Af[((size_t)m16 * K8CNT + k8) * 32 + lane] =
            make_uint4(f2tf32(a00), f2tf32(a10), f2tf32(a01), f2tf32(a11));
    }
}

// ---------------------------------------------------------------------------
// TF32 GEMM (round-13 proven body, UNCHANGED): fragment-direct
// ---------------------------------------------------------------------------
template <bool GUARD_N>
__global__ __launch_bounds__(256, 2) void tf32_gemm(
    const uint4* __restrict__ Af, const uint4* __restrict__ Bf,
    float* __restrict__ C, int ldC, int Nvalid, const float* __restrict__ bias) {
    const int tid = threadIdx.x;
    const int lane = tid & 31;
    const int warp = tid >> 5;
    const int wm = warp >> 1;
    const int wn = warp & 1;

    const uint4* Ap = Af + ((size_t)(blockIdx.y * 8 + wm * 2) * K8CNT) * 32 + lane;
    const uint4* Bp = Bf + ((size_t)(blockIdx.x * 16 + wn * 8) * KPCNT) * 32 + lane;

    float acc[2][8][4];
#pragma unroll
    for (int mi = 0; mi < 2; mi++)
#pragma unroll
        for (int ni = 0; ni < 8; ni++)
#pragma unroll
            for (int j = 0; j < 4; j++) acc[mi][ni][j] = 0.0f;

    for (int kp = 0; kp < KPCNT; kp++) {
        uint4 b4[8];
#pragma unroll
        for (int ni = 0; ni < 8; ni++)
            b4[ni] = Bp[((size_t)ni * KPCNT + kp) * 32];
        uint4 a4[2][2];
#pragma unroll
        for (int s = 0; s < 2; s++)
#pragma unroll
            for (int mi = 0; mi < 2; mi++)
                a4[s][mi] = Ap[((size_t)mi * K8CNT + 2 * kp + s) * 32];

#pragma unroll
        for (int s = 0; s < 2; s++)
#pragma unroll
            for (int mi = 0; mi < 2; mi++)
#pragma unroll
                for (int ni = 0; ni < 8; ni++) {
                    uint32_t bx = s ? b4[ni].z : b4[ni].x;
                    uint32_t by = s ? b4[ni].w : b4[ni].y;
                    asm volatile(
                        "mma.sync.aligned.m16n8k8.row.col.f32.tf32.tf32.f32 "
                        "{%0,%1,%2,%3}, {%4,%5,%6,%7}, {%8,%9}, {%0,%1,%2,%3};\n"
                        : "+f"(acc[mi][ni][0]), "+f"(acc[mi][ni][1]),
                          "+f"(acc[mi][ni][2]), "+f"(acc[mi][ni][3])
                        : "r"(a4[s][mi].x), "r"(a4[s][mi].y),
                          "r"(a4[s][mi].z), "r"(a4[s][mi].w),
                          "r"(bx), "r"(by));
                }
    }

    const int gr = lane >> 2;
    const int gc = (lane & 3) * 2;
#pragma unroll
    for (int mi = 0; mi < 2; mi++) {
        int r0 = blockIdx.y * 128 + wm * 32 + mi * 16 + gr;
#pragma unroll
        for (int ni = 0; ni < 8; ni++) {
            int c0 = blockIdx.x * 128 + wn * 64 + ni * 8 + gc;
            float b0 = 0.0f, b1 = 0.0f;
            if (bias) {
                if (!GUARD_N || c0 < Nvalid) b0 = bias[c0];
                if (!GUARD_N || c0 + 1 < Nvalid) b1 = bias[c0 + 1];
            }
            float* Cp0 = C + (size_t)r0 * ldC + c0;
            float* Cp1 = C + (size_t)(r0 + 8) * ldC + c0;
            if (!GUARD_N || c0 < Nvalid) {
                Cp0[0] = acc[mi][ni][0] + b0;
                Cp1[0] = acc[mi][ni][2] + b0;
            }
            if (!GUARD_N || c0 + 1 < Nvalid) {
                Cp0[1] = acc[mi][ni][1] + b1;
                Cp1[1] = acc[mi][ni][3] + b1;
            }
        }
    }
}

// ---------------------------------------------------------------------------
// Fused SRU scan (round-13 mapping: ONE THREAD PER (b,h), 131072 threads)
// + t+1 PREFETCH: next iteration's 4 loads issue before this iteration's
// sigmoid/FMA chain -> 2x memory-level parallelism. Arithmetic identical.
// ---------------------------------------------------------------------------
__global__ void sru_scan_frag_kernel(const float* __restrict__ U,
                                     uint32_t* __restrict__ Afw,
                                     const float* __restrict__ bfp,
                                     const float* __restrict__ brp,
                                     float* __restrict__ c_out) {
    const int idx = blockIdx.x * blockDim.x + threadIdx.x;   // 0..131071
    const int b = idx >> 10;
    const int h = idx & 1023;

    const int bg = b >> 4, bsel = (b >> 3) & 1, gr = b & 7;
    const int k8 = h >> 3, hsel = (h >> 2) & 1, gc = h & 3;
    const int lane = gr * 4 + gc;
    const int comp = bsel + 2 * hsel;

    const float bfv = bfp[h];
    const float brv = brp[h];
    float c = 0.0f;

    const float* Ub = U + (size_t)b * N_SRU + h;
    uint32_t* Ab = Afw + ((size_t)bg * K8CNT + k8) * 128 + lane * 4 + comp;
    const size_t uStep = (size_t)B_DIM * N_SRU;
    const size_t aStep = (size_t)8 * K8CNT * 128;

    // prologue: loads for t=0
    float z = Ub[0];
    float fp = Ub[H_DIM];
    float rp = Ub[2 * H_DIM];
    uint32_t hb = *Ab;

    for (int t = 0; t < T_DIM; t++) {
        // prefetch t+1 (independent of the recurrence below)
        float zn = 0.0f, fpn = 0.0f, rpn = 0.0f;
        uint32_t hbn = 0;
        if (t + 1 < T_DIM) {
            const float* Un = Ub + (size_t)(t + 1) * uStep;
            zn = Un[0];
            fpn = Un[H_DIM];
            rpn = Un[2 * H_DIM];
            hbn = Ab[(size_t)(t + 1) * aStep];
        }
        float f = 1.0f / (1.0f + __expf(-(fp + bfv)));
        float r = 1.0f / (1.0f + __expf(-(rp + brv)));
        c = f * c + (1.0f - f) * z;
        Ab[(size_t)t * aStep] =
            f2tf32(r * c + (1.0f - r) * __uint_as_float(hb));
        z = zn; fp = fpn; rp = rpn; hb = hbn;
    }
    c_out[idx] = c;
}

// ---------------------------------------------------------------------------
// Launch
// ---------------------------------------------------------------------------
extern "C" void kernel_launch(void* const* d_in, const int* in_sizes, int n_in,
                              void* d_out, int out_size) {
    const float* x     = (const float*)d_in[0];
    const float* W1    = (const float*)d_in[2];
    const float* b1    = (const float*)d_in[3];
    const float* W_sru = (const float*)d_in[4];
    const float* bf    = (const float*)d_in[5];
    const float* br    = (const float*)d_in[6];
    const float* W3    = (const float*)d_in[7];
    const float* b3    = (const float*)d_in[8];
    float* out = (float*)d_out;

    float *U_buf, *WTf, *W3Tf;
    uint4* Af;
    cudaGetSymbolAddress((void**)&U_buf, g_U);
    cudaGetSymbolAddress((void**)&Af, g_Af);
    cudaGetSymbolAddress((void**)&WTf, g_WT);
    cudaGetSymbolAddress((void**)&W3Tf, g_W3T);
    uint4* BF = (uint4*)WTf;
    uint4* BF3 = (uint4*)W3Tf;
    const size_t bfLayerStride = (size_t)N8_SRU * KPCNT * 32;

    {
        dim3 grd(N8_SRU * KPCNT / 8, 4);
        wfrag_all_kernel<<<grd, 256>>>(W_sru, W3, BF, BF3, bfLayerStride);
    }

    dense1_frag_kernel<<<M_ALL / 16, 256>>>(x, W1, b1, Af);

    float* c_base = out + (size_t)M_ALL * OUT_DIM;
    for (int l = 0; l < L_DIM; l++) {
        dim3 grid(N_SRU / 128, M_ALL / 128);
        tf32_gemm<false><<<grid, 256>>>(
            Af, BF + l * bfLayerStride, U_buf, N_SRU, N_SRU, nullptr);
        sru_scan_frag_kernel<<<(B_DIM * H_DIM) / 256, 256>>>(
            U_buf, (uint32_t*)Af, bf + l * H_DIM, br + l * H_DIM,
            c_base + (size_t)l * B_DIM * H_DIM);
    }

    dim3 grid3(N3PAD / 128, M_ALL / 128);
    tf32_gemm<true><<<grid3, 256>>>(Af, BF3, out, OUT_DIM, OUT_DIM, b3);
}

// round 16
// speedup vs baseline: 1.2139x; 1.0312x over previous
#include <cuda_runtime.h>
#include <cstdint>

#define T_DIM 256
#define B_DIM 128
#define DIN 20
#define H_DIM 1024
#define OUT_DIM 1095
#define L_DIM 3
#define M_ALL (T_DIM * B_DIM)   // 32768
#define N_SRU (3 * H_DIM)       // 3072
#define N3PAD 1152
#define K8CNT (H_DIM / 8)       // 128
#define KPCNT (K8CNT / 2)       // 64
#define N8_SRU (N_SRU / 8)      // 384
#define N8_W3 (N3PAD / 8)       // 144

// ---------------- scratch ----------------
__device__ float g_U[(size_t)M_ALL * N_SRU];                      // 402 MB
__device__ uint4 g_Af[(size_t)(M_ALL / 16) * K8CNT * 32];         // 134 MB
__device__ float g_WT[(size_t)L_DIM * N_SRU * H_DIM];             // B frags (SRU)
__device__ float g_W3T[(size_t)N3PAD * H_DIM];                    // B frags (W3)

__device__ __forceinline__ uint32_t f2tf32(float v) {
    uint32_t u;
    asm("cvt.rna.tf32.f32 %0, %1;" : "=r"(u) : "f"(v));
    return u;
}

// ---------------------------------------------------------------------------
// Prep B (all layers, one launch): W[K][N] -> fragment-pair order (n8-major)
// ---------------------------------------------------------------------------
__global__ void wfrag_all_kernel(const float* __restrict__ Wsru,
                                 const float* __restrict__ W3,
                                 uint4* __restrict__ BF,
                                 uint4* __restrict__ BF3,
                                 size_t layerStride) {
    const int layer = blockIdx.y;
    const float* W;
    uint4* dst;
    int N, N8;
    if (layer < 3) {
        W = Wsru + (size_t)layer * H_DIM * N_SRU;
        dst = BF + (size_t)layer * layerStride;
        N = N_SRU; N8 = N8_SRU;
    } else {
        W = W3; dst = BF3; N = OUT_DIM; N8 = N8_W3;
    }
    int task = blockIdx.x * 8 + (threadIdx.x >> 5);
    if (task >= N8 * KPCNT) return;
    int n8 = task / KPCNT;
    int kp = task - n8 * KPCNT;
    int lane = threadIdx.x & 31;
    int n = n8 * 8 + (lane >> 2);
    int kq = kp * 16 + (lane & 3);
    float b0 = 0.0f, b1 = 0.0f, b2 = 0.0f, b3 = 0.0f;
    if (n < N) {
        b0 = W[(size_t)kq * N + n];
        b1 = W[(size_t)(kq + 4) * N + n];
        b2 = W[(size_t)(kq + 8) * N + n];
        b3 = W[(size_t)(kq + 12) * N + n];
    }
    dst[((size_t)n8 * KPCNT + kp) * 32 + lane] =
        make_uint4(f2tf32(b0), f2tf32(b1), f2tf32(b2), f2tf32(b3));
}

// ---------------------------------------------------------------------------
// Dense1 -> A fragments directly (verified)
// ---------------------------------------------------------------------------
__global__ void dense1_frag_kernel(const float* __restrict__ x,
                                   const float* __restrict__ W1,
                                   const float* __restrict__ b1v,
                                   uint4* __restrict__ Af) {
    const int m16 = blockIdx.x;
    const int t = m16 >> 3, bg = m16 & 7;
    __shared__ float xs[16][20];
    for (int i = threadIdx.x; i < 16 * DIN; i += blockDim.x) {
        int r = i / DIN, cc = i - r * DIN;
        xs[r][cc] = x[((size_t)t * B_DIM + bg * 16 + r) * DIN + cc];
    }
    __syncthreads();
    const int w = threadIdx.x >> 5, lane = threadIdx.x & 31;
    const int gr = lane >> 2, gc = lane & 3;
    for (int kb = 0; kb < 16; kb++) {
        int k8 = kb * 8 + w;
        int h0 = k8 * 8 + gc, h1 = h0 + 4;
        float a00 = b1v[h0], a01 = b1v[h1];
        float a10 = a00, a11 = a01;
#pragma unroll
        for (int k = 0; k < DIN; k++) {
            float w0 = W1[k * H_DIM + h0], w1 = W1[k * H_DIM + h1];
            float x0 = xs[gr][k], x1 = xs[gr + 8][k];
            a00 += x0 * w0; a01 += x0 * w1;
            a10 += x1 * w0; a11 += x1 * w1;
        }
        Af[((size_t)m16 * K8CNT + k8) * 32 + lane] =
            make_uint4(f2tf32(a00), f2tf32(a10), f2tf32(a01), f2tf32(a11));
    }
}

// ---------------------------------------------------------------------------
// TF32 GEMM (round-13 proven body, UNCHANGED): fragment-direct
// ---------------------------------------------------------------------------
template <bool GUARD_N>
__global__ __launch_bounds__(256, 2) void tf32_gemm(
    const uint4* __restrict__ Af, const uint4* __restrict__ Bf,
    float* __restrict__ C, int ldC, int Nvalid, const float* __restrict__ bias) {
    const int tid = threadIdx.x;
    const int lane = tid & 31;
    const int warp = tid >> 5;
    const int wm = warp >> 1;
    const int wn = warp & 1;

    const uint4* Ap = Af + ((size_t)(blockIdx.y * 8 + wm * 2) * K8CNT) * 32 + lane;
    const uint4* Bp = Bf + ((size_t)(blockIdx.x * 16 + wn * 8) * KPCNT) * 32 + lane;

    float acc[2][8][4];
#pragma unroll
    for (int mi = 0; mi < 2; mi++)
#pragma unroll
        for (int ni = 0; ni < 8; ni++)
#pragma unroll
            for (int j = 0; j < 4; j++) acc[mi][ni][j] = 0.0f;

    for (int kp = 0; kp < KPCNT; kp++) {
        uint4 b4[8];
#pragma unroll
        for (int ni = 0; ni < 8; ni++)
            b4[ni] = Bp[((size_t)ni * KPCNT + kp) * 32];
        uint4 a4[2][2];
#pragma unroll
        for (int s = 0; s < 2; s++)
#pragma unroll
            for (int mi = 0; mi < 2; mi++)
                a4[s][mi] = Ap[((size_t)mi * K8CNT + 2 * kp + s) * 32];

#pragma unroll
        for (int s = 0; s < 2; s++)
#pragma unroll
            for (int mi = 0; mi < 2; mi++)
#pragma unroll
                for (int ni = 0; ni < 8; ni++) {
                    uint32_t bx = s ? b4[ni].z : b4[ni].x;
                    uint32_t by = s ? b4[ni].w : b4[ni].y;
                    asm volatile(
                        "mma.sync.aligned.m16n8k8.row.col.f32.tf32.tf32.f32 "
                        "{%0,%1,%2,%3}, {%4,%5,%6,%7}, {%8,%9}, {%0,%1,%2,%3};\n"
                        : "+f"(acc[mi][ni][0]), "+f"(acc[mi][ni][1]),
                          "+f"(acc[mi][ni][2]), "+f"(acc[mi][ni][3])
                        : "r"(a4[s][mi].x), "r"(a4[s][mi].y),
                          "r"(a4[s][mi].z), "r"(a4[s][mi].w),
                          "r"(bx), "r"(by));
                }
    }

    const int gr = lane >> 2;
    const int gc = (lane & 3) * 2;
#pragma unroll
    for (int mi = 0; mi < 2; mi++) {
        int r0 = blockIdx.y * 128 + wm * 32 + mi * 16 + gr;
#pragma unroll
        for (int ni = 0; ni < 8; ni++) {
            int c0 = blockIdx.x * 128 + wn * 64 + ni * 8 + gc;
            float b0 = 0.0f, b1 = 0.0f;
            if (bias) {
                if (!GUARD_N || c0 < Nvalid) b0 = bias[c0];
                if (!GUARD_N || c0 + 1 < Nvalid) b1 = bias[c0 + 1];
            }
            float* Cp0 = C + (size_t)r0 * ldC + c0;
            float* Cp1 = C + (size_t)(r0 + 8) * ldC + c0;
            if (!GUARD_N || c0 < Nvalid) {
                Cp0[0] = acc[mi][ni][0] + b0;
                Cp1[0] = acc[mi][ni][2] + b0;
            }
            if (!GUARD_N || c0 + 1 < Nvalid) {
                Cp0[1] = acc[mi][ni][1] + b1;
                Cp1[1] = acc[mi][ni][3] + b1;
            }
        }
    }
}

// ---------------------------------------------------------------------------
// Fused SRU scan: one thread per (b,h), PREFETCH DISTANCE 2 (8 loads in
// flight). Arithmetic/order identical -> bit-identical result.
// ---------------------------------------------------------------------------
__global__ void sru_scan_frag_kernel(const float* __restrict__ U,
                                     uint32_t* __restrict__ Afw,
                                     const float* __restrict__ bfp,
                                     const float* __restrict__ brp,
                                     float* __restrict__ c_out) {
    const int idx = blockIdx.x * blockDim.x + threadIdx.x;   // 0..131071
    const int b = idx >> 10;
    const int h = idx & 1023;

    const int bg = b >> 4, bsel = (b >> 3) & 1, gr = b & 7;
    const int k8 = h >> 3, hsel = (h >> 2) & 1, gc = h & 3;
    const int lane = gr * 4 + gc;
    const int comp = bsel + 2 * hsel;

    const float bfv = bfp[h];
    const float brv = brp[h];
    float c = 0.0f;

    const float* Ub = U + (size_t)b * N_SRU + h;
    uint32_t* Ab = Afw + ((size_t)bg * K8CNT + k8) * 128 + lane * 4 + comp;
    const size_t uStep = (size_t)B_DIM * N_SRU;
    const size_t aStep = (size_t)8 * K8CNT * 128;

    // pipeline registers: stage 0 = t, stage 1 = t+1
    float z0 = Ub[0], fp0 = Ub[H_DIM], rp0 = Ub[2 * H_DIM];
    uint32_t hb0 = *Ab;
    const float* U1 = Ub + uStep;
    float z1 = U1[0], fp1 = U1[H_DIM], rp1 = U1[2 * H_DIM];
    uint32_t hb1 = Ab[aStep];

    for (int t = 0; t < T_DIM; t++) {
        // prefetch t+2
        float zn = 0.0f, fpn = 0.0f, rpn = 0.0f;
        uint32_t hbn = 0;
        if (t + 2 < T_DIM) {
            const float* Un = Ub + (size_t)(t + 2) * uStep;
            zn = Un[0];
            fpn = Un[H_DIM];
            rpn = Un[2 * H_DIM];
            hbn = Ab[(size_t)(t + 2) * aStep];
        }
        float f = 1.0f / (1.0f + __expf(-(fp0 + bfv)));
        float r = 1.0f / (1.0f + __expf(-(rp0 + brv)));
        c = f * c + (1.0f - f) * z0;
        Ab[(size_t)t * aStep] =
            f2tf32(r * c + (1.0f - r) * __uint_as_float(hb0));
        z0 = z1; fp0 = fp1; rp0 = rp1; hb0 = hb1;
        z1 = zn; fp1 = fpn; rp1 = rpn; hb1 = hbn;
    }
    c_out[idx] = c;
}

// ---------------------------------------------------------------------------
// Launch
// ---------------------------------------------------------------------------
extern "C" void kernel_launch(void* const* d_in, const int* in_sizes, int n_in,
                              void* d_out, int out_size) {
    const float* x     = (const float*)d_in[0];
    const float* W1    = (const float*)d_in[2];
    const float* b1    = (const float*)d_in[3];
    const float* W_sru = (const float*)d_in[4];
    const float* bf    = (const float*)d_in[5];
    const float* br    = (const float*)d_in[6];
    const float* W3    = (const float*)d_in[7];
    const float* b3    = (const float*)d_in[8];
    float* out = (float*)d_out;

    float *U_buf, *WTf, *W3Tf;
    uint4* Af;
    cudaGetSymbolAddress((void**)&U_buf, g_U);
    cudaGetSymbolAddress((void**)&Af, g_Af);
    cudaGetSymbolAddress((void**)&WTf, g_WT);
    cudaGetSymbolAddress((void**)&W3Tf, g_W3T);
    uint4* BF = (uint4*)WTf;
    uint4* BF3 = (uint4*)W3Tf;
    const size_t bfLayerStride = (size_t)N8_SRU * KPCNT * 32;

    {
        dim3 grd(N8_SRU * KPCNT / 8, 4);
        wfrag_all_kernel<<<grd, 256>>>(W_sru, W3, BF, BF3, bfLayerStride);
    }

    dense1_frag_kernel<<<M_ALL / 16, 256>>>(x, W1, b1, Af);

    float* c_base = out + (size_t)M_ALL * OUT_DIM;
    for (int l = 0; l < L_DIM; l++) {
        dim3 grid(N_SRU / 128, M_ALL / 128);
        tf32_gemm<false><<<grid, 256>>>(
            Af, BF + l * bfLayerStride, U_buf, N_SRU, N_SRU, nullptr);
        sru_scan_frag_kernel<<<(B_DIM * H_DIM) / 256, 256>>>(
            U_buf, (uint32_t*)Af, bf + l * H_DIM, br + l * H_DIM,
            c_base + (size_t)l * B_DIM * H_DIM);
    }

    dim3 grid3(N3PAD / 128, M_ALL / 128);
    tf32_gemm<true><<<grid3, 256>>>(Af, BF3, out, OUT_DIM, OUT_DIM, b3);
}